// round 10
// baseline (speedup 1.0000x reference)
#include <cuda_runtime.h>
#include <cstdint>

#define B    256
#define T    2048
#define HID  128
#define ATT  8

#define NCTA 148
#define NWPC 16                      // warps per CTA
#define THREADS (NWPC * 32)
#define NWTOT (NCTA * NWPC)          // 2368 warps
#define NTILES_TOT (B * T / 8)       // 65536 tiles of 8 rows

#define TR 8
#define TILE_F4 (TR * 32)            // 4 KB per tile
#define NSTAGE 3
#define WBYTES (NSTAGE * TILE_F4 * 16)   // 12 KB per warp
#define SMEM_TOTAL (NWPC * WBYTES)       // 192 KB

__device__ float g_p[B * HID];
__device__ float g_pv[NWTOT][2][HID];
__device__ float g_ps[NWTOT][2];
__device__ int   g_cnt[B];           // zero-init; winner resets

__device__ __forceinline__ void cp_async16(uint32_t dst, const void* src) {
    asm volatile("cp.async.cg.shared.global [%0], [%1], 16;\n"
                 :: "r"(dst), "l"(src) : "memory");
}
__device__ __forceinline__ void cp_commit() {
    asm volatile("cp.async.commit_group;\n" ::: "memory");
}
template<int N> __device__ __forceinline__ void cp_wait() {
    asm volatile("cp.async.wait_group %0;\n" :: "n"(N) : "memory");
}
__device__ __forceinline__ uint32_t smem_u32(const void* p) {
    return (uint32_t)__cvta_generic_to_shared(p);
}

#define FULL 0xffffffffu

// ---- kernel 0: p[b][h] = sum_a Wx[h,a] * (sum_h' H[b,T-1,h'] * Wt[h',a]) ----
__global__ void __launch_bounds__(HID)
mata_p(const float* __restrict__ H,
       const float* __restrict__ Wt,
       const float* __restrict__ Wx)
{
    __shared__ float s_wt[HID * ATT];
    __shared__ float s_red[4][ATT];
    __shared__ float s_q[ATT];

    const int b    = blockIdx.x;
    const int tid  = threadIdx.x;
    const int wid  = tid >> 5;
    const int lane = tid & 31;

    #pragma unroll
    for (int i = 0; i < ATT; i++) s_wt[tid + i * HID] = Wt[tid + i * HID];

    const float hl = __ldg(H + (size_t)b * T * HID + (size_t)(T - 1) * HID + tid);
    __syncthreads();

    float qa[ATT];
    #pragma unroll
    for (int a = 0; a < ATT; a++) {
        float v = hl * s_wt[tid * ATT + a];
        #pragma unroll
        for (int off = 16; off > 0; off >>= 1)
            v += __shfl_xor_sync(FULL, v, off);
        qa[a] = v;
    }
    if (lane == 0) {
        #pragma unroll
        for (int a = 0; a < ATT; a++) s_red[wid][a] = qa[a];
    }
    __syncthreads();
    if (tid < ATT)
        s_q[tid] = s_red[0][tid] + s_red[1][tid] + s_red[2][tid] + s_red[3][tid];
    __syncthreads();

    float pv = 0.f;
    #pragma unroll
    for (int a = 0; a < ATT; a++) pv += __ldg(Wx + tid * ATT + a) * s_q[a];
    g_p[b * HID + tid] = pv;
}

// ---- main: 148 fat CTAs, per-warp exact tile partition, zero CTA syncs ----
__global__ void __launch_bounds__(THREADS)
mata_main(const float* __restrict__ H,
          const float* __restrict__ mask,
          const float* __restrict__ rate,
          const float* __restrict__ obs_bias,
          const float* __restrict__ miss_bias,
          float* __restrict__ v_out,
          float* __restrict__ a_out)
{
    extern __shared__ __align__(16) char s_mem[];

    const int tid  = threadIdx.x;
    const int wid  = tid >> 5;
    const int lane = tid & 31;
    const int wg   = blockIdx.x * NWPC + wid;          // global warp 0..2367

    const int ts = (wg * 1024) / 37;                   // exact partition
    const int te = ((wg + 1) * 1024) / 37;
    const int bf = ts >> 8;                            // first batch (256 tiles/batch)
    const int bsplit = min(te, (bf + 1) << 8);         // batch boundary (tile units)
    const bool crossed = (te > bsplit);

    float4* mybuf = (float4*)(s_mem + wid * WBYTES);
    const uint32_t mybuf_u = smem_u32(mybuf);

    // prologue prefetch (range always >= 27 tiles > NSTAGE)
    #pragma unroll
    for (int p = 0; p < NSTAGE; p++) {
        const float4* src = (const float4*)(H + (size_t)(ts + p) * TR * HID);
        const uint32_t dbase = mybuf_u + p * TILE_F4 * 16;
        #pragma unroll
        for (int j = 0; j < TR; j++)
            cp_async16(dbase + (j * 32 + lane) * 16, src + j * 32 + lane);
        cp_commit();
    }

    const float4 pv0 = __ldg((const float4*)(g_p + bf * HID) + lane);
    const float4 pv1 = crossed ? __ldg((const float4*)(g_p + (bf + 1) * HID) + lane) : pv0;

    const float sr = 1.f / (1.f + __expf(-__ldg(rate)));
    const float ob = __ldg(obs_bias);
    const float mb = __ldg(miss_bias);

    const int vrow = (lane >> 2) & 7;

    float4 acc  = make_float4(0.f, 0.f, 0.f, 0.f);
    float  sumw = 0.f;
    int slot = 0;

    #pragma unroll 1
    for (int tile = ts; tile < te; tile++) {
        // flush partial at batch boundary
        if (tile == bsplit) {
            ((float4*)&g_pv[wg][0][0])[lane] = acc;
            if (lane == 0) g_ps[wg][0] = sumw;
            acc = make_float4(0.f, 0.f, 0.f, 0.f);
            sumw = 0.f;
        }

        const int grow = tile * TR + vrow;             // global row (flat over B*T)
        const float m = __ldg(mask + grow);

        cp_wait<2>();

        const float4* buf = mybuf + slot * TILE_F4;
        const float4 pvs = (tile < bsplit) ? pv0 : pv1;

        float4 tv[TR];
        #pragma unroll
        for (int j = 0; j < TR; j++) tv[j] = buf[j * 32 + lane];

        float d[TR];
        #pragma unroll
        for (int j = 0; j < TR; j++)
            d[j] = tv[j].x * pvs.x + tv[j].y * pvs.y + tv[j].z * pvs.z + tv[j].w * pvs.w;

        if (tile + NSTAGE < te) {
            const float4* src = (const float4*)(H + (size_t)(tile + NSTAGE) * TR * HID);
            const uint32_t dbase = mybuf_u + slot * TILE_F4 * 16;
            #pragma unroll
            for (int j = 0; j < TR; j++)
                cp_async16(dbase + (j * 32 + lane) * 16, src + j * 32 + lane);
            cp_commit();
        }

        // value-halving cross-lane reduction: 9 shuffles
        const bool hi16 = (lane & 16) != 0;
        float e[4];
        #pragma unroll
        for (int j = 0; j < 4; j++) {
            float x = hi16 ? d[j] : d[j + 4];
            float r = __shfl_xor_sync(FULL, x, 16);
            e[j] = (hi16 ? d[j + 4] : d[j]) + r;
        }
        const bool hi8 = (lane & 8) != 0;
        float f[2];
        #pragma unroll
        for (int j = 0; j < 2; j++) {
            float x = hi8 ? e[j] : e[j + 2];
            float r = __shfl_xor_sync(FULL, x, 8);
            f[j] = (hi8 ? e[j + 2] : e[j]) + r;
        }
        const bool hi4 = (lane & 4) != 0;
        {
            float x = hi4 ? f[0] : f[1];
            float r = __shfl_xor_sync(FULL, x, 4);
            f[0] = (hi4 ? f[1] : f[0]) + r;
        }
        f[0] += __shfl_xor_sync(FULL, f[0], 1);
        f[0] += __shfl_xor_sync(FULL, f[0], 2);

        const int t_in = grow & (T - 1);
        const float s   = 1.f / (1.f + __expf(-f[0]));
        const float bt  = (float)(T - t_in);
        const float den = sr * (__logf(2.72f + (1.f - s)) * bt);
        const float e2  = fmaxf(s / den, 0.f);
        const float w   = __expf(e2 + (m > 0.5f ? ob : mb));

        if ((lane & 3) == 0) a_out[grow] = w;

        #pragma unroll
        for (int r2 = 0; r2 < TR; r2++) {
            const float wr = __shfl_sync(FULL, w, r2 << 2);
            acc.x += wr * tv[r2].x; acc.y += wr * tv[r2].y;
            acc.z += wr * tv[r2].z; acc.w += wr * tv[r2].w;
            sumw  += wr;
        }

        slot = (slot == NSTAGE - 1) ? 0 : slot + 1;
    }

    // final flush
    {
        const int j = crossed ? 1 : 0;
        ((float4*)&g_pv[wg][j][0])[lane] = acc;
        if (lane == 0) g_ps[wg][j] = sumw;
    }
    __threadfence();

    // per-batch winner election + normalization (warp-local, deterministic values)
    #pragma unroll 1
    for (int jj = 0; jj < (crossed ? 2 : 1); jj++) {
        const int b = bf + jj;
        const int wF = (37 * b) >> 2;                          // floor(37b/4)
        const int wL = (37 * (256 * b + 255)) >> 10;           // floor(.../1024)
        const int K  = wL - wF + 1;

        int old = 0;
        if (lane == 0) old = atomicAdd(&g_cnt[b], 1);
        old = __shfl_sync(FULL, old, 0);
        if (old != K - 1) continue;

        __threadfence();

        float4 vsum = make_float4(0.f, 0.f, 0.f, 0.f);
        float  ssum = 0.f;
        for (int w2 = wF; w2 <= wL; w2++) {
            const int bf2 = ((w2 * 1024) / 37) >> 8;
            const int j2  = (bf2 == b) ? 0 : 1;
            const float4 pvv = ((const float4*)&g_pv[w2][j2][0])[lane];
            vsum.x += pvv.x; vsum.y += pvv.y; vsum.z += pvv.z; vsum.w += pvv.w;
            ssum += g_ps[w2][j2];
        }
        const float inv = 1.f / ssum;

        ((float4*)(v_out + b * HID))[lane] =
            make_float4(vsum.x * inv, vsum.y * inv, vsum.z * inv, vsum.w * inv);

        float4* ab4 = (float4*)(a_out + (size_t)b * T);
        #pragma unroll
        for (int i = lane; i < T / 4; i += 32) {
            float4 x = ab4[i];
            x.x *= inv; x.y *= inv; x.z *= inv; x.w *= inv;
            ab4[i] = x;
        }

        if (lane == 0) g_cnt[b] = 0;   // reset for next replay
    }
}

extern "C" void kernel_launch(void* const* d_in, const int* in_sizes, int n_in,
                              void* d_out, int out_size)
{
    const float* H   = (const float*)d_in[0];
    const float* msk = (const float*)d_in[1];
    const float* Wt  = (const float*)d_in[2];
    const float* Wx  = (const float*)d_in[3];
    const float* rt  = (const float*)d_in[4];
    const float* ob  = (const float*)d_in[5];
    const float* mb  = (const float*)d_in[6];

    float* v_out = (float*)d_out;               // [B, HID]
    float* a_out = (float*)d_out + B * HID;     // [B, T]

    static int smem_set = 0;
    if (!smem_set) {
        cudaFuncSetAttribute(mata_main,
                             cudaFuncAttributeMaxDynamicSharedMemorySize, SMEM_TOTAL);
        smem_set = 1;
    }

    mata_p<<<B, HID>>>(H, Wt, Wx);
    mata_main<<<NCTA, THREADS, SMEM_TOTAL>>>(H, msk, rt, ob, mb, v_out, a_out);
}

// round 12
// speedup vs baseline: 1.0981x; 1.0981x over previous
#include <cuda_runtime.h>
#include <cstdint>

#define B    256
#define T    2048
#define HID  128
#define ATT  8

#define NCTA 592                     // 4 per SM, one uniform wave
#define NW   4
#define THREADS (NW * 32)
#define NWTOT (NCTA * NW)            // 2368 warps
                                     // 65536 tiles / 2368 = 1024/37 exactly
#define TR 8
#define TILE_F4 (TR * 32)            // 4 KB per tile
#define NSTAGE 3
#define WBYTES (NSTAGE * TILE_F4 * 16)   // 12 KB per warp

__device__ float g_p[B * HID];
__device__ float g_pv[NWTOT][2][HID];
__device__ float g_ps[NWTOT][2];
__device__ int   g_cnt[B];           // zero-init; winner resets

__device__ __forceinline__ void cp_async16(uint32_t dst, const void* src) {
    asm volatile("cp.async.cg.shared.global [%0], [%1], 16;\n"
                 :: "r"(dst), "l"(src) : "memory");
}
__device__ __forceinline__ void cp_commit() {
    asm volatile("cp.async.commit_group;\n" ::: "memory");
}
template<int N> __device__ __forceinline__ void cp_wait() {
    asm volatile("cp.async.wait_group %0;\n" :: "n"(N) : "memory");
}
__device__ __forceinline__ uint32_t smem_u32(const void* p) {
    return (uint32_t)__cvta_generic_to_shared(p);
}

#define FULL 0xffffffffu

// ---- kernel 0: p[b][h] = sum_a Wx[h,a] * (sum_h' H[b,T-1,h'] * Wt[h',a]) ----
__global__ void __launch_bounds__(HID)
mata_p(const float* __restrict__ H,
       const float* __restrict__ Wt,
       const float* __restrict__ Wx)
{
    __shared__ float s_wt[HID * ATT];
    __shared__ float s_red[4][ATT];
    __shared__ float s_q[ATT];

    const int b    = blockIdx.x;
    const int tid  = threadIdx.x;
    const int wid  = tid >> 5;
    const int lane = tid & 31;

    #pragma unroll
    for (int i = 0; i < ATT; i++) s_wt[tid + i * HID] = Wt[tid + i * HID];

    const float hl = __ldg(H + (size_t)b * T * HID + (size_t)(T - 1) * HID + tid);
    __syncthreads();

    float qa[ATT];
    #pragma unroll
    for (int a = 0; a < ATT; a++) {
        float v = hl * s_wt[tid * ATT + a];
        #pragma unroll
        for (int off = 16; off > 0; off >>= 1)
            v += __shfl_xor_sync(FULL, v, off);
        qa[a] = v;
    }
    if (lane == 0) {
        #pragma unroll
        for (int a = 0; a < ATT; a++) s_red[wid][a] = qa[a];
    }
    __syncthreads();
    if (tid < ATT)
        s_q[tid] = s_red[0][tid] + s_red[1][tid] + s_red[2][tid] + s_red[3][tid];
    __syncthreads();

    float pv = 0.f;
    #pragma unroll
    for (int a = 0; a < ATT; a++) pv += __ldg(Wx + tid * ATT + a) * s_q[a];
    g_p[b * HID + tid] = pv;
}

// hot-loop body, identical to the proven R8 inner loop (no batch logic)
#define TILE_BODY(PVV)                                                         \
{                                                                              \
    const int grow = tile * TR + vrow;                                         \
    const float m = __ldg(mask + grow);                                        \
    cp_wait<2>();                                                              \
    const float4* buf = mybuf + slot * TILE_F4;                                \
    float4 tv[TR];                                                             \
    _Pragma("unroll")                                                          \
    for (int j = 0; j < TR; j++) tv[j] = buf[j * 32 + lane];                   \
    float d[TR];                                                               \
    _Pragma("unroll")                                                          \
    for (int j = 0; j < TR; j++)                                               \
        d[j] = tv[j].x * PVV.x + tv[j].y * PVV.y + tv[j].z * PVV.z + tv[j].w * PVV.w; \
    if (tile + NSTAGE < te) {                                                  \
        const float4* src = (const float4*)(H + (size_t)(tile + NSTAGE) * TR * HID); \
        const uint32_t dbase = mybuf_u + slot * TILE_F4 * 16;                  \
        _Pragma("unroll")                                                      \
        for (int j = 0; j < TR; j++)                                           \
            cp_async16(dbase + (j * 32 + lane) * 16, src + j * 32 + lane);     \
        cp_commit();                                                           \
    }                                                                          \
    const bool hi16 = (lane & 16) != 0;                                        \
    float e[4];                                                                \
    _Pragma("unroll")                                                          \
    for (int j = 0; j < 4; j++) {                                              \
        float x = hi16 ? d[j] : d[j + 4];                                      \
        float r = __shfl_xor_sync(FULL, x, 16);                                \
        e[j] = (hi16 ? d[j + 4] : d[j]) + r;                                   \
    }                                                                          \
    const bool hi8 = (lane & 8) != 0;                                          \
    float f[2];                                                                \
    _Pragma("unroll")                                                          \
    for (int j = 0; j < 2; j++) {                                              \
        float x = hi8 ? e[j] : e[j + 2];                                       \
        float r = __shfl_xor_sync(FULL, x, 8);                                 \
        f[j] = (hi8 ? e[j + 2] : e[j]) + r;                                    \
    }                                                                          \
    const bool hi4 = (lane & 4) != 0;                                          \
    {                                                                          \
        float x = hi4 ? f[0] : f[1];                                           \
        float r = __shfl_xor_sync(FULL, x, 4);                                 \
        f[0] = (hi4 ? f[1] : f[0]) + r;                                        \
    }                                                                          \
    f[0] += __shfl_xor_sync(FULL, f[0], 1);                                    \
    f[0] += __shfl_xor_sync(FULL, f[0], 2);                                    \
    const int t_in = ((tile & 255) << 3) + vrow;                               \
    const float s   = 1.f / (1.f + __expf(-f[0]));                             \
    const float bt  = (float)(T - t_in);                                       \
    const float den = sr * (__logf(2.72f + (1.f - s)) * bt);                   \
    const float e2  = fmaxf(s / den, 0.f);                                     \
    const float w   = __expf(e2 + (m > 0.5f ? ob : mb));                       \
    if ((lane & 3) == 0) a_out[grow] = w;                                      \
    _Pragma("unroll")                                                          \
    for (int r2 = 0; r2 < TR; r2++) {                                          \
        const float wr = __shfl_sync(FULL, w, r2 << 2);                        \
        acc.x += wr * tv[r2].x; acc.y += wr * tv[r2].y;                        \
        acc.z += wr * tv[r2].z; acc.w += wr * tv[r2].w;                        \
        sumw  += wr;                                                           \
    }                                                                          \
    slot = (slot == NSTAGE - 1) ? 0 : slot + 1;                                \
}

__global__ void __launch_bounds__(THREADS)
mata_main(const float* __restrict__ H,
          const float* __restrict__ mask,
          const float* __restrict__ rate,
          const float* __restrict__ obs_bias,
          const float* __restrict__ miss_bias,
          float* __restrict__ v_out,
          float* __restrict__ a_out)
{
    __shared__ __align__(16) char s_mem[NW * WBYTES];   // 48 KB static

    const int tid  = threadIdx.x;
    const int wid  = tid >> 5;
    const int lane = tid & 31;
    const int wg   = blockIdx.x * NW + wid;            // global warp 0..2367

    const int ts = (wg * 1024) / 37;                   // exact partition, 27-28 tiles
    const int te = ((wg + 1) * 1024) / 37;
    const int bf = ts >> 8;
    const int bsplit = min(te, (bf + 1) << 8);
    const bool crossed = (te > bsplit);

    float4* mybuf = (float4*)(s_mem + wid * WBYTES);
    const uint32_t mybuf_u = smem_u32(mybuf);

    // prologue prefetch
    #pragma unroll
    for (int p = 0; p < NSTAGE; p++) {
        const float4* src = (const float4*)(H + (size_t)(ts + p) * TR * HID);
        const uint32_t dbase = mybuf_u + p * TILE_F4 * 16;
        #pragma unroll
        for (int j = 0; j < TR; j++)
            cp_async16(dbase + (j * 32 + lane) * 16, src + j * 32 + lane);
        cp_commit();
    }

    const float4 pv0 = __ldg((const float4*)(g_p + bf * HID) + lane);

    const float sr = 1.f / (1.f + __expf(-__ldg(rate)));
    const float ob = __ldg(obs_bias);
    const float mb = __ldg(miss_bias);

    const int vrow = (lane >> 2) & 7;

    float4 acc  = make_float4(0.f, 0.f, 0.f, 0.f);
    float  sumw = 0.f;
    int slot = 0;

    // ---- loop 1: tiles in batch bf (clean hot body) ----
    #pragma unroll 1
    for (int tile = ts; tile < bsplit; tile++) TILE_BODY(pv0)

    if (crossed) {
        ((float4*)&g_pv[wg][0][0])[lane] = acc;
        if (lane == 0) g_ps[wg][0] = sumw;
        acc = make_float4(0.f, 0.f, 0.f, 0.f);
        sumw = 0.f;

        const float4 pv1 = __ldg((const float4*)(g_p + (bf + 1) * HID) + lane);
        // ---- loop 2: tiles in batch bf+1 ----
        #pragma unroll 1
        for (int tile = bsplit; tile < te; tile++) TILE_BODY(pv1)
    }

    {
        const int j = crossed ? 1 : 0;
        ((float4*)&g_pv[wg][j][0])[lane] = acc;
        if (lane == 0) g_ps[wg][j] = sumw;
    }
    __threadfence();

    // ---- per-batch winner election + normalization (deterministic order) ----
    #pragma unroll 1
    for (int jj = 0; jj < (crossed ? 2 : 1); jj++) {
        const int b = bf + jj;
        const int wF = (37 * b) >> 2;
        const int wL = (37 * (256 * b + 255)) >> 10;
        const int K  = wL - wF + 1;

        int old = 0;
        if (lane == 0) old = atomicAdd(&g_cnt[b], 1);
        old = __shfl_sync(FULL, old, 0);
        if (old != K - 1) continue;

        __threadfence();

        float4 vsum = make_float4(0.f, 0.f, 0.f, 0.f);
        float  ssum = 0.f;
        for (int w2 = wF; w2 <= wL; w2++) {
            const int bf2 = ((w2 * 1024) / 37) >> 8;
            const int j2  = (bf2 == b) ? 0 : 1;
            const float4 pvv = ((const float4*)&g_pv[w2][j2][0])[lane];
            vsum.x += pvv.x; vsum.y += pvv.y; vsum.z += pvv.z; vsum.w += pvv.w;
            ssum += g_ps[w2][j2];
        }
        const float inv = 1.f / ssum;

        ((float4*)(v_out + b * HID))[lane] =
            make_float4(vsum.x * inv, vsum.y * inv, vsum.z * inv, vsum.w * inv);

        float4* ab4 = (float4*)(a_out + (size_t)b * T);
        #pragma unroll
        for (int i = lane; i < T / 4; i += 32) {
            float4 x = ab4[i];
            x.x *= inv; x.y *= inv; x.z *= inv; x.w *= inv;
            ab4[i] = x;
        }

        if (lane == 0) g_cnt[b] = 0;   // reset for next replay
    }
}

extern "C" void kernel_launch(void* const* d_in, const int* in_sizes, int n_in,
                              void* d_out, int out_size)
{
    const float* H   = (const float*)d_in[0];
    const float* msk = (const float*)d_in[1];
    const float* Wt  = (const float*)d_in[2];
    const float* Wx  = (const float*)d_in[3];
    const float* rt  = (const float*)d_in[4];
    const float* ob  = (const float*)d_in[5];
    const float* mb  = (const float*)d_in[6];

    float* v_out = (float*)d_out;               // [B, HID]
    float* a_out = (float*)d_out + B * HID;     // [B, T]

    mata_p<<<B, HID>>>(H, Wt, Wx);
    mata_main<<<NCTA, THREADS>>>(H, msk, rt, ob, mb, v_out, a_out);
}

// round 13
// speedup vs baseline: 1.1759x; 1.0709x over previous
#include <cuda_runtime.h>
#include <cstdint>

#define B   256
#define T   2048
#define HID 128
#define ATT 8

#define SPLIT 2                    // CTAs per batch
#define CHUNK (T / SPLIT)          // 1024 rows per CTA
#define NW 4                       // warps per CTA
#define THREADS (NW * 32)
#define ROWS_PER_WARP (CHUNK / NW) // 256
#define TR 8                       // rows per tile
#define NTILES (ROWS_PER_WARP / TR)// 32
#define TILE_F4 (TR * 32)          // 256 float4 per tile (4 KB)
#define NSTAGE 3
#define WBYTES (NSTAGE * TILE_F4 * 16)   // 12 KB per-warp buffer

__device__ float g_partial_v[B * SPLIT * HID];
__device__ float g_partial_s[B * SPLIT];
__device__ int   g_cnt[B];               // zero-init; winner resets

__device__ __forceinline__ void cp_async16(uint32_t dst, const void* src) {
    asm volatile("cp.async.cg.shared.global [%0], [%1], 16;\n"
                 :: "r"(dst), "l"(src) : "memory");
}
__device__ __forceinline__ void cp_commit() {
    asm volatile("cp.async.commit_group;\n" ::: "memory");
}
template<int N> __device__ __forceinline__ void cp_wait() {
    asm volatile("cp.async.wait_group %0;\n" :: "n"(N) : "memory");
}
__device__ __forceinline__ uint32_t smem_u32(const void* p) {
    return (uint32_t)__cvta_generic_to_shared(p);
}

#define FULL 0xffffffffu

__global__ void __launch_bounds__(THREADS)
mata_main(const float* __restrict__ H,
          const float* __restrict__ mask,
          const float* __restrict__ Wt,
          const float* __restrict__ Wx,
          const float* __restrict__ rate,
          const float* __restrict__ obs_bias,
          const float* __restrict__ miss_bias,
          float* __restrict__ v_out,
          float* __restrict__ a_out)
{
    __shared__ __align__(16) char s_mem[NW * WBYTES];   // 48 KB tile buffers
    __shared__ float s_sred[NW];
    __shared__ float s_red[NW][ATT];
    __shared__ __align__(16) float s_p[HID];
    __shared__ int   s_last;

    const int bx   = blockIdx.x;
    const int b    = bx / SPLIT;
    const int c    = bx % SPLIT;
    const int tid  = threadIdx.x;
    const int wid  = tid >> 5;
    const int lane = tid & 31;

    const float* Hb = H + (size_t)b * T * HID;
    const int t0w = c * CHUNK + wid * ROWS_PER_WARP;

    float4* mybuf = (float4*)(s_mem + wid * WBYTES);
    const uint32_t mybuf_u = smem_u32(mybuf);

    // ---- prologue: launch 3-tile prefetch immediately ----
    #pragma unroll
    for (int p = 0; p < NSTAGE; p++) {
        const float4* src = (const float4*)(Hb + (size_t)(t0w + p * TR) * HID);
        const uint32_t dbase = mybuf_u + p * TILE_F4 * 16;
        #pragma unroll
        for (int j = 0; j < TR; j++)
            cp_async16(dbase + (j * 32 + lane) * 16, src + j * 32 + lane);
        cp_commit();
    }

    // ---- fused q/p computation (overlaps with prefetch in flight) ----
    {
        const float  hl  = __ldg(Hb + (size_t)(T - 1) * HID + tid);
        const float4 wt0 = __ldg((const float4*)(Wt + tid * ATT));
        const float4 wt1 = __ldg((const float4*)(Wt + tid * ATT) + 1);
        float qa[ATT];
        qa[0] = hl * wt0.x; qa[1] = hl * wt0.y; qa[2] = hl * wt0.z; qa[3] = hl * wt0.w;
        qa[4] = hl * wt1.x; qa[5] = hl * wt1.y; qa[6] = hl * wt1.z; qa[7] = hl * wt1.w;
        #pragma unroll
        for (int off = 16; off > 0; off >>= 1) {
            #pragma unroll
            for (int a = 0; a < ATT; a++)
                qa[a] += __shfl_xor_sync(FULL, qa[a], off);
        }
        if (lane == 0) {
            #pragma unroll
            for (int a = 0; a < ATT; a++) s_red[wid][a] = qa[a];
        }
        __syncthreads();
        float q[ATT];
        #pragma unroll
        for (int a = 0; a < ATT; a++)
            q[a] = s_red[0][a] + s_red[1][a] + s_red[2][a] + s_red[3][a];
        const float4 wx0 = __ldg((const float4*)(Wx + tid * ATT));
        const float4 wx1 = __ldg((const float4*)(Wx + tid * ATT) + 1);
        s_p[tid] = wx0.x * q[0] + wx0.y * q[1] + wx0.z * q[2] + wx0.w * q[3]
                 + wx1.x * q[4] + wx1.y * q[5] + wx1.z * q[6] + wx1.w * q[7];
        __syncthreads();
    }
    const float4 pv = ((const float4*)s_p)[lane];

    const float sr = 1.f / (1.f + __expf(-__ldg(rate)));
    const float ob = __ldg(obs_bias);
    const float mb = __ldg(miss_bias);

    const float* __restrict__ mrow = mask + (size_t)b * T;
    float* __restrict__ arow = a_out + (size_t)b * T;

    const int vrow = (lane >> 2) & 7;

    float4 acc  = make_float4(0.f, 0.f, 0.f, 0.f);
    float  sumw = 0.f;
    int slot = 0;

    #pragma unroll 1
    for (int kt = 0; kt < NTILES; kt++) {
        const int tbase = t0w + kt * TR;
        const float m = __ldcs(mrow + tbase + vrow);   // streaming: touched once

        cp_wait<2>();   // tile kt resident, two more in flight

        const float4* buf = mybuf + slot * TILE_F4;

        float4 tv[TR];
        #pragma unroll
        for (int j = 0; j < TR; j++) tv[j] = buf[j * 32 + lane];

        float d[TR];
        #pragma unroll
        for (int j = 0; j < TR; j++)
            d[j] = tv[j].x * pv.x + tv[j].y * pv.y + tv[j].z * pv.z + tv[j].w * pv.w;

        if (kt + NSTAGE < NTILES) {
            const float4* src = (const float4*)(Hb + (size_t)(t0w + (kt + NSTAGE) * TR) * HID);
            const uint32_t dbase = mybuf_u + slot * TILE_F4 * 16;
            #pragma unroll
            for (int j = 0; j < TR; j++)
                cp_async16(dbase + (j * 32 + lane) * 16, src + j * 32 + lane);
            cp_commit();
        }

        // value-halving cross-lane reduction: 9 shuffles
        const bool hi16 = (lane & 16) != 0;
        float e[4];
        #pragma unroll
        for (int j = 0; j < 4; j++) {
            float x = hi16 ? d[j] : d[j + 4];
            float r = __shfl_xor_sync(FULL, x, 16);
            e[j] = (hi16 ? d[j + 4] : d[j]) + r;
        }
        const bool hi8 = (lane & 8) != 0;
        float f[2];
        #pragma unroll
        for (int j = 0; j < 2; j++) {
            float x = hi8 ? e[j] : e[j + 2];
            float r = __shfl_xor_sync(FULL, x, 8);
            f[j] = (hi8 ? e[j + 2] : e[j]) + r;
        }
        const bool hi4 = (lane & 4) != 0;
        {
            float x = hi4 ? f[0] : f[1];
            float r = __shfl_xor_sync(FULL, x, 4);
            f[0] = (hi4 ? f[1] : f[0]) + r;
        }
        f[0] += __shfl_xor_sync(FULL, f[0], 1);
        f[0] += __shfl_xor_sync(FULL, f[0], 2);

        const int t = tbase + vrow;
        const float s   = 1.f / (1.f + __expf(-f[0]));
        const float bt  = (float)(T - t);
        const float den = sr * (__logf(2.72f + (1.f - s)) * bt);
        const float e2  = fmaxf(s / den, 0.f);
        const float w   = __expf(e2 + (m > 0.5f ? ob : mb));

        if ((lane & 3) == 0) __stcs(arow + t, w);      // streaming store

        #pragma unroll
        for (int r2 = 0; r2 < TR; r2++) {
            const float wr = __shfl_sync(FULL, w, r2 << 2);
            acc.x += wr * tv[r2].x; acc.y += wr * tv[r2].y;
            acc.z += wr * tv[r2].z; acc.w += wr * tv[r2].w;
            sumw  += wr;
        }

        slot = (slot == NSTAGE - 1) ? 0 : slot + 1;
    }

    // ---- CTA reduction (vred overlays dead tile buffers) ----
    cp_wait<0>();
    __syncwarp();
    ((float4*)(s_mem + wid * WBYTES))[lane] = acc;
    if (lane == 0) s_sred[wid] = sumw;
    __syncthreads();

    if (tid < HID) {
        float v = 0.f;
        #pragma unroll
        for (int w = 0; w < NW; w++)
            v += ((float*)(s_mem + w * WBYTES))[tid];
        g_partial_v[((size_t)b * SPLIT + c) * HID + tid] = v;
    }
    if (tid == 0) {
        float ss = 0.f;
        #pragma unroll
        for (int w = 0; w < NW; w++) ss += s_sred[w];
        g_partial_s[b * SPLIT + c] = ss;
    }

    // ---- fused epilogue: last CTA of this batch normalizes ----
    __threadfence();
    __syncthreads();
    if (tid == 0) {
        int old = atomicAdd(&g_cnt[b], 1);
        s_last = (old == SPLIT - 1) ? 1 : 0;
    }
    __syncthreads();
    if (!s_last) return;
    __threadfence();

    float ss = 0.f;
    #pragma unroll
    for (int cc = 0; cc < SPLIT; cc++) ss += g_partial_s[b * SPLIT + cc];
    const float inv = 1.f / ss;

    if (tid < HID) {
        float v = 0.f;
        #pragma unroll
        for (int cc = 0; cc < SPLIT; cc++)
            v += g_partial_v[((size_t)b * SPLIT + cc) * HID + tid];
        v_out[(size_t)b * HID + tid] = v * inv;
    }

    float4* ab4 = (float4*)arow;
    #pragma unroll
    for (int i = tid; i < T / 4; i += THREADS) {
        float4 x = ab4[i];
        x.x *= inv; x.y *= inv; x.z *= inv; x.w *= inv;
        __stcs(ab4 + i, x);
    }

    if (tid == 0) g_cnt[b] = 0;   // reset for next graph replay
}

extern "C" void kernel_launch(void* const* d_in, const int* in_sizes, int n_in,
                              void* d_out, int out_size)
{
    const float* H   = (const float*)d_in[0];
    const float* msk = (const float*)d_in[1];
    const float* Wt  = (const float*)d_in[2];
    const float* Wx  = (const float*)d_in[3];
    const float* rt  = (const float*)d_in[4];
    const float* ob  = (const float*)d_in[5];
    const float* mb  = (const float*)d_in[6];

    float* v_out = (float*)d_out;               // [B, HID]
    float* a_out = (float*)d_out + B * HID;     // [B, T]

    mata_main<<<B * SPLIT, THREADS>>>(H, msk, Wt, Wx, rt, ob, mb, v_out, a_out);
}

// round 14
// speedup vs baseline: 1.2724x; 1.0820x over previous
#include <cuda_runtime.h>
#include <cstdint>

#define B   256
#define T   2048
#define HID 128
#define ATT 8

#define SPLIT 2                    // CTAs per batch
#define CHUNK (T / SPLIT)          // 1024 rows per CTA
#define NW 4                       // warps per CTA
#define THREADS (NW * 32)
#define ROWS_PER_WARP (CHUNK / NW) // 256
#define TR 8                       // rows per tile
#define NTILES (ROWS_PER_WARP / TR)// 32
#define TILE_F4 (TR * 32)          // 256 float4 per tile (4 KB)
#define NSTAGE 3
#define WBYTES (NSTAGE * TILE_F4 * 16)   // 12 KB per-warp buffer

__device__ float g_partial_v[B * SPLIT * HID];
__device__ float g_partial_s[B * SPLIT];
__device__ int   g_cnt[B];               // zero-init; winner resets

// cp.async with L2 evict-first hint: H is streamed exactly once; keep the
// small hot set (unnormalized a, partials) resident in L2 for the epilogue.
__device__ __forceinline__ void cp_async16_ef(uint32_t dst, const void* src,
                                              uint64_t policy) {
    asm volatile("cp.async.cg.shared.global.L2::cache_hint [%0], [%1], 16, %2;\n"
                 :: "r"(dst), "l"(src), "l"(policy) : "memory");
}
__device__ __forceinline__ uint64_t mk_evict_first_policy() {
    uint64_t p;
    asm volatile("createpolicy.fractional.L2::evict_first.b64 %0, 1.0;\n" : "=l"(p));
    return p;
}
__device__ __forceinline__ void cp_commit() {
    asm volatile("cp.async.commit_group;\n" ::: "memory");
}
template<int N> __device__ __forceinline__ void cp_wait() {
    asm volatile("cp.async.wait_group %0;\n" :: "n"(N) : "memory");
}
__device__ __forceinline__ uint32_t smem_u32(const void* p) {
    return (uint32_t)__cvta_generic_to_shared(p);
}

#define FULL 0xffffffffu

__global__ void __launch_bounds__(THREADS)
mata_main(const float* __restrict__ H,
          const float* __restrict__ mask,
          const float* __restrict__ Wt,
          const float* __restrict__ Wx,
          const float* __restrict__ rate,
          const float* __restrict__ obs_bias,
          const float* __restrict__ miss_bias,
          float* __restrict__ v_out,
          float* __restrict__ a_out)
{
    __shared__ __align__(16) char s_mem[NW * WBYTES];   // 48 KB tile buffers
    __shared__ float s_sred[NW];
    __shared__ float s_red[NW][ATT];
    __shared__ __align__(16) float s_p[HID];
    __shared__ int   s_last;

    const int bx   = blockIdx.x;
    const int b    = bx / SPLIT;
    const int c    = bx % SPLIT;
    const int tid  = threadIdx.x;
    const int wid  = tid >> 5;
    const int lane = tid & 31;

    const float* Hb = H + (size_t)b * T * HID;
    const int t0w = c * CHUNK + wid * ROWS_PER_WARP;

    float4* mybuf = (float4*)(s_mem + wid * WBYTES);
    const uint32_t mybuf_u = smem_u32(mybuf);
    const uint64_t pol = mk_evict_first_policy();

    // ---- prologue: launch 3-tile prefetch immediately ----
    #pragma unroll
    for (int p = 0; p < NSTAGE; p++) {
        const float4* src = (const float4*)(Hb + (size_t)(t0w + p * TR) * HID);
        const uint32_t dbase = mybuf_u + p * TILE_F4 * 16;
        #pragma unroll
        for (int j = 0; j < TR; j++)
            cp_async16_ef(dbase + (j * 32 + lane) * 16, src + j * 32 + lane, pol);
        cp_commit();
    }

    // ---- fused q/p computation (overlaps with prefetch in flight) ----
    {
        const float  hl  = __ldg(Hb + (size_t)(T - 1) * HID + tid);
        const float4 wt0 = __ldg((const float4*)(Wt + tid * ATT));
        const float4 wt1 = __ldg((const float4*)(Wt + tid * ATT) + 1);
        float qa[ATT];
        qa[0] = hl * wt0.x; qa[1] = hl * wt0.y; qa[2] = hl * wt0.z; qa[3] = hl * wt0.w;
        qa[4] = hl * wt1.x; qa[5] = hl * wt1.y; qa[6] = hl * wt1.z; qa[7] = hl * wt1.w;
        #pragma unroll
        for (int off = 16; off > 0; off >>= 1) {
            #pragma unroll
            for (int a = 0; a < ATT; a++)
                qa[a] += __shfl_xor_sync(FULL, qa[a], off);
        }
        if (lane == 0) {
            #pragma unroll
            for (int a = 0; a < ATT; a++) s_red[wid][a] = qa[a];
        }
        __syncthreads();
        float q[ATT];
        #pragma unroll
        for (int a = 0; a < ATT; a++)
            q[a] = s_red[0][a] + s_red[1][a] + s_red[2][a] + s_red[3][a];
        const float4 wx0 = __ldg((const float4*)(Wx + tid * ATT));
        const float4 wx1 = __ldg((const float4*)(Wx + tid * ATT) + 1);
        s_p[tid] = wx0.x * q[0] + wx0.y * q[1] + wx0.z * q[2] + wx0.w * q[3]
                 + wx1.x * q[4] + wx1.y * q[5] + wx1.z * q[6] + wx1.w * q[7];
        __syncthreads();
    }
    const float4 pv = ((const float4*)s_p)[lane];

    const float sr = 1.f / (1.f + __expf(-__ldg(rate)));
    const float ob = __ldg(obs_bias);
    const float mb = __ldg(miss_bias);

    const float* __restrict__ mrow = mask + (size_t)b * T;
    float* __restrict__ arow = a_out + (size_t)b * T;

    const int vrow = (lane >> 2) & 7;

    float4 acc  = make_float4(0.f, 0.f, 0.f, 0.f);
    float  sumw = 0.f;
    int slot = 0;

    #pragma unroll 1
    for (int kt = 0; kt < NTILES; kt++) {
        const int tbase = t0w + kt * TR;
        const float m = __ldcs(mrow + tbase + vrow);   // read once: streaming load

        cp_wait<2>();   // tile kt resident, two more in flight

        const float4* buf = mybuf + slot * TILE_F4;

        float4 tv[TR];
        #pragma unroll
        for (int j = 0; j < TR; j++) tv[j] = buf[j * 32 + lane];

        float d[TR];
        #pragma unroll
        for (int j = 0; j < TR; j++)
            d[j] = tv[j].x * pv.x + tv[j].y * pv.y + tv[j].z * pv.z + tv[j].w * pv.w;

        if (kt + NSTAGE < NTILES) {
            const float4* src = (const float4*)(Hb + (size_t)(t0w + (kt + NSTAGE) * TR) * HID);
            const uint32_t dbase = mybuf_u + slot * TILE_F4 * 16;
            #pragma unroll
            for (int j = 0; j < TR; j++)
                cp_async16_ef(dbase + (j * 32 + lane) * 16, src + j * 32 + lane, pol);
            cp_commit();
        }

        // value-halving cross-lane reduction: 9 shuffles
        const bool hi16 = (lane & 16) != 0;
        float e[4];
        #pragma unroll
        for (int j = 0; j < 4; j++) {
            float x = hi16 ? d[j] : d[j + 4];
            float r = __shfl_xor_sync(FULL, x, 16);
            e[j] = (hi16 ? d[j + 4] : d[j]) + r;
        }
        const bool hi8 = (lane & 8) != 0;
        float f[2];
        #pragma unroll
        for (int j = 0; j < 2; j++) {
            float x = hi8 ? e[j] : e[j + 2];
            float r = __shfl_xor_sync(FULL, x, 8);
            f[j] = (hi8 ? e[j + 2] : e[j]) + r;
        }
        const bool hi4 = (lane & 4) != 0;
        {
            float x = hi4 ? f[0] : f[1];
            float r = __shfl_xor_sync(FULL, x, 4);
            f[0] = (hi4 ? f[1] : f[0]) + r;
        }
        f[0] += __shfl_xor_sync(FULL, f[0], 1);
        f[0] += __shfl_xor_sync(FULL, f[0], 2);

        const int t = tbase + vrow;
        const float s   = 1.f / (1.f + __expf(-f[0]));
        const float bt  = (float)(T - t);
        const float den = sr * (__logf(2.72f + (1.f - s)) * bt);
        const float e2  = fmaxf(s / den, 0.f);
        const float w   = __expf(e2 + (m > 0.5f ? ob : mb));

        if ((lane & 3) == 0) arow[t] = w;   // plain store: re-read by winner (L2-resident)

        #pragma unroll
        for (int r2 = 0; r2 < TR; r2++) {
            const float wr = __shfl_sync(FULL, w, r2 << 2);
            acc.x += wr * tv[r2].x; acc.y += wr * tv[r2].y;
            acc.z += wr * tv[r2].z; acc.w += wr * tv[r2].w;
            sumw  += wr;
        }

        slot = (slot == NSTAGE - 1) ? 0 : slot + 1;
    }

    // ---- CTA reduction (vred overlays dead tile buffers) ----
    cp_wait<0>();
    __syncwarp();
    ((float4*)(s_mem + wid * WBYTES))[lane] = acc;
    if (lane == 0) s_sred[wid] = sumw;
    __syncthreads();

    if (tid < HID) {
        float v = 0.f;
        #pragma unroll
        for (int w = 0; w < NW; w++)
            v += ((float*)(s_mem + w * WBYTES))[tid];
        g_partial_v[((size_t)b * SPLIT + c) * HID + tid] = v;
    }
    if (tid == 0) {
        float ss = 0.f;
        #pragma unroll
        for (int w = 0; w < NW; w++) ss += s_sred[w];
        g_partial_s[b * SPLIT + c] = ss;
    }

    // ---- fused epilogue: last CTA of this batch normalizes ----
    __threadfence();
    __syncthreads();
    if (tid == 0) {
        int old = atomicAdd(&g_cnt[b], 1);
        s_last = (old == SPLIT - 1) ? 1 : 0;
    }
    __syncthreads();
    if (!s_last) return;
    __threadfence();

    float ss = 0.f;
    #pragma unroll
    for (int cc = 0; cc < SPLIT; cc++) ss += g_partial_s[b * SPLIT + cc];
    const float inv = 1.f / ss;

    if (tid < HID) {
        float v = 0.f;
        #pragma unroll
        for (int cc = 0; cc < SPLIT; cc++)
            v += g_partial_v[((size_t)b * SPLIT + cc) * HID + tid];
        v_out[(size_t)b * HID + tid] = v * inv;
    }

    float4* ab4 = (float4*)arow;
    #pragma unroll
    for (int i = tid; i < T / 4; i += THREADS) {
        float4 x = ab4[i];
        x.x *= inv; x.y *= inv; x.z *= inv; x.w *= inv;
        ab4[i] = x;
    }

    if (tid == 0) g_cnt[b] = 0;   // reset for next graph replay
}

extern "C" void kernel_launch(void* const* d_in, const int* in_sizes, int n_in,
                              void* d_out, int out_size)
{
    const float* H   = (const float*)d_in[0];
    const float* msk = (const float*)d_in[1];
    const float* Wt  = (const float*)d_in[2];
    const float* Wx  = (const float*)d_in[3];
    const float* rt  = (const float*)d_in[4];
    const float* ob  = (const float*)d_in[5];
    const float* mb  = (const float*)d_in[6];

    float* v_out = (float*)d_out;               // [B, HID]
    float* a_out = (float*)d_out + B * HID;     // [B, T]

    mata_main<<<B * SPLIT, THREADS>>>(H, msk, Wt, Wx, rt, ob, mb, v_out, a_out);
}